// round 5
// baseline (speedup 1.0000x reference)
#include <cuda_runtime.h>
#include <cstdint>

// ---------------------------------------------------------------------------
// Problem constants
// ---------------------------------------------------------------------------
#define B_SZ     8
#define N_PTS    131072
#define IN_C     64
#define OUT_C    64
#define STYLE_D  256
#define EPS_V    1e-8f

// Per-batch modulated+demodulated weight, stored TRANSPOSED: gW[b][i][o]
__device__ float g_W[B_SZ * IN_C * OUT_C];

// ---------------------------------------------------------------------------
// Kernel A: build the 8 modulated/demodulated 64x64 weight matrices.
// grid = B_SZ blocks, 64 threads each. Negligible cost (~few us).
// ---------------------------------------------------------------------------
__global__ void modw_kernel(const float* __restrict__ style,
                            const float* __restrict__ weight,
                            const float* __restrict__ mod_weight,
                            const float* __restrict__ mod_bias) {
    const int b = blockIdx.x;
    const int t = threadIdx.x;             // 0..63
    __shared__ float s_sh[IN_C];

    // s_i = (style[b] . mod_weight[i]) * (1/sqrt(256)) + mod_bias[i] + 1
    const float mod_scale = 0.0625f;       // 1/16
    const float* st = style + b * STYLE_D;
    const float* mw = mod_weight + t * STYLE_D;
    float acc = 0.f;
    #pragma unroll 8
    for (int d = 0; d < STYLE_D; d += 4) {
        float4 a = *(const float4*)(st + d);
        float4 m = *(const float4*)(mw + d);
        acc += a.x * m.x + a.y * m.y + a.z * m.z + a.w * m.w;
    }
    s_sh[t] = acc * mod_scale + mod_bias[t] + 1.0f;
    __syncthreads();

    // row o = t : w[o][i] = (1/8) * weight[o][i] * s[i];  demod over i
    const float scale = 0.125f;            // 1/sqrt(64)
    const float* wr = weight + t * IN_C;
    float ss = 0.f;
    #pragma unroll 16
    for (int i = 0; i < IN_C; i++) {
        float v = scale * wr[i] * s_sh[i];
        ss += v * v;
    }
    float demod = rsqrtf(ss + EPS_V);
    float* outp = g_W + b * IN_C * OUT_C;
    #pragma unroll 16
    for (int i = 0; i < IN_C; i++) {
        float v = scale * wr[i] * s_sh[i];
        outp[i * OUT_C + t] = v * demod;   // transposed [i][o]
    }
}

// ---------------------------------------------------------------------------
// Packed f32x2 FMA (ptxas never auto-fuses this; PTX-only per SASS_QUICKREF)
// ---------------------------------------------------------------------------
__device__ __forceinline__ void fma2(unsigned long long& d,
                                     unsigned long long a,
                                     unsigned long long b) {
    asm volatile("fma.rn.f32x2 %0, %1, %2, %0;" : "+l"(d) : "l"(a), "l"(b));
}
__device__ __forceinline__ float f2lo(unsigned long long v) {
    return __uint_as_float((unsigned)(v & 0xffffffffull));
}
__device__ __forceinline__ float f2hi(unsigned long long v) {
    return __uint_as_float((unsigned)(v >> 32));
}

// ---------------------------------------------------------------------------
// Kernel B: per-batch GEMM  out[128,64] = Xtile[128,64] @ W_b^T  per block.
// Block = 256 threads; thread tile = 8 points (as 4 f32x2 pairs) x 4 outs.
// Xs: X transposed [k][p] (32KB). Wsd: W duplicated (w,w) [k][o] (32KB).
// ---------------------------------------------------------------------------
__global__ __launch_bounds__(256, 3)
void modconv_kernel(const float* __restrict__ x,
                    const float* __restrict__ bias,
                    float* __restrict__ out) {
    __shared__ float  Xs[IN_C][128];       // [k][p]   32 KB
    __shared__ float2 Wsd[IN_C][OUT_C];    // [k][o] duplicated, 32 KB

    const int b   = blockIdx.y;
    const int tid = threadIdx.x;
    const long base = ((long)b * N_PTS + (long)blockIdx.x * 128) * IN_C;
    const float* xin = x + base;

    // ---- stage X tile, transposed ----
    #pragma unroll
    for (int it = 0; it < 8; it++) {
        int idx = tid + it * 256;          // 0..2047
        int p   = idx & 127;
        int i4  = idx >> 7;                // 0..15
        float4 v = *(const float4*)(xin + (long)p * IN_C + i4 * 4);
        Xs[i4 * 4 + 0][p] = v.x;
        Xs[i4 * 4 + 1][p] = v.y;
        Xs[i4 * 4 + 2][p] = v.z;
        Xs[i4 * 4 + 3][p] = v.w;
    }
    // ---- stage W (transposed in gmem already), duplicate for f32x2 ----
    const float* Wb = g_W + b * IN_C * OUT_C;
    #pragma unroll
    for (int it = 0; it < 16; it++) {
        int idx = tid + it * 256;          // 0..4095 = [k][o]
        float w = Wb[idx];
        Wsd[idx >> 6][idx & 63] = make_float2(w, w);
    }
    __syncthreads();

    const int og = tid & 15;               // 16 output groups of 4
    const int pg = tid >> 4;               // 16 point  groups of 8
    const int p0 = pg * 8;
    const int o0 = og * 4;

    unsigned long long acc[4][4];          // [point-pair][out]
    #pragma unroll
    for (int i = 0; i < 4; i++)
        #pragma unroll
        for (int j = 0; j < 4; j++) acc[i][j] = 0ull;

    #pragma unroll 8
    for (int k = 0; k < IN_C; k++) {
        const ulonglong2* xp = (const ulonglong2*)&Xs[k][p0];
        ulonglong2 xa0 = xp[0];
        ulonglong2 xa1 = xp[1];
        unsigned long long a2[4] = { xa0.x, xa0.y, xa1.x, xa1.y };

        const ulonglong2* wp = (const ulonglong2*)&Wsd[k][o0];
        ulonglong2 wv0 = wp[0];
        ulonglong2 wv1 = wp[1];
        unsigned long long b2[4] = { wv0.x, wv0.y, wv1.x, wv1.y };

        #pragma unroll
        for (int pp = 0; pp < 4; pp++)
            #pragma unroll
            for (int oo = 0; oo < 4; oo++)
                fma2(acc[pp][oo], a2[pp], b2[oo]);
    }

    // ---- epilogue: add bias, store coalesced float4 per point ----
    float4 bv = *(const float4*)(bias + o0);
    float* op = out + base;
    #pragma unroll
    for (int pp = 0; pp < 4; pp++) {
        int pe = p0 + pp * 2;
        float4 r0, r1;
        r0.x = f2lo(acc[pp][0]) + bv.x;  r1.x = f2hi(acc[pp][0]) + bv.x;
        r0.y = f2lo(acc[pp][1]) + bv.y;  r1.y = f2hi(acc[pp][1]) + bv.y;
        r0.z = f2lo(acc[pp][2]) + bv.z;  r1.z = f2hi(acc[pp][2]) + bv.z;
        r0.w = f2lo(acc[pp][3]) + bv.w;  r1.w = f2hi(acc[pp][3]) + bv.w;
        *(float4*)(op + (long)pe       * OUT_C + o0) = r0;
        *(float4*)(op + (long)(pe + 1) * OUT_C + o0) = r1;
    }
}

// ---------------------------------------------------------------------------
// Launch
// inputs: 0=x, 1=style, 2=weight, 3=bias, 4=mod_weight, 5=mod_bias
// ---------------------------------------------------------------------------
extern "C" void kernel_launch(void* const* d_in, const int* in_sizes, int n_in,
                              void* d_out, int out_size) {
    const float* x          = (const float*)d_in[0];
    const float* style      = (const float*)d_in[1];
    const float* weight     = (const float*)d_in[2];
    const float* bias       = (const float*)d_in[3];
    const float* mod_weight = (const float*)d_in[4];
    const float* mod_bias   = (const float*)d_in[5];
    float* out = (float*)d_out;

    modw_kernel<<<B_SZ, 64>>>(style, weight, mod_weight, mod_bias);

    dim3 grid(N_PTS / 128, B_SZ);
    modconv_kernel<<<grid, 256>>>(x, bias, out);
}

// round 7
// speedup vs baseline: 1.0947x; 1.0947x over previous
#include <cuda_runtime.h>
#include <cstdint>

// ---------------------------------------------------------------------------
// Problem constants
// ---------------------------------------------------------------------------
#define B_SZ     8
#define N_PTS    131072
#define IN_C     64
#define OUT_C    64
#define STYLE_D  256
#define EPS_V    1e-8f

// Per-batch modulated+demodulated weight, stored K-BLOCKED:
//   g_W[b][k4][o][kin]  (k = k4*4 + kin), 4096 floats per batch.
__device__ float g_W[B_SZ * IN_C * OUT_C];

// ---------------------------------------------------------------------------
// Kernel A: build the 8 modulated/demodulated 64x64 weight matrices.
// grid = B_SZ blocks, 64 threads each. Negligible cost.
// ---------------------------------------------------------------------------
__global__ void modw_kernel(const float* __restrict__ style,
                            const float* __restrict__ weight,
                            const float* __restrict__ mod_weight,
                            const float* __restrict__ mod_bias) {
    const int b = blockIdx.x;
    const int t = threadIdx.x;             // 0..63  (= output channel o)
    __shared__ float s_sh[IN_C];

    // s_i = (style[b] . mod_weight[i]) * (1/sqrt(256)) + mod_bias[i] + 1
    const float mod_scale = 0.0625f;       // 1/16
    const float* st = style + b * STYLE_D;
    const float* mw = mod_weight + t * STYLE_D;
    float acc = 0.f;
    #pragma unroll 8
    for (int d = 0; d < STYLE_D; d += 4) {
        float4 a = *(const float4*)(st + d);
        float4 m = *(const float4*)(mw + d);
        acc += a.x * m.x + a.y * m.y + a.z * m.z + a.w * m.w;
    }
    s_sh[t] = acc * mod_scale + mod_bias[t] + 1.0f;
    __syncthreads();

    // row o = t : w[o][i] = (1/8) * weight[o][i] * s[i];  demod over i
    const float scale = 0.125f;            // 1/sqrt(64)
    const float* wr = weight + t * IN_C;
    float ss = 0.f;
    #pragma unroll 16
    for (int i = 0; i < IN_C; i++) {
        float v = scale * wr[i] * s_sh[i];
        ss += v * v;
    }
    float demod = rsqrtf(ss + EPS_V);
    float* outp = g_W + b * IN_C * OUT_C;
    #pragma unroll 16
    for (int i = 0; i < IN_C; i++) {
        float v = scale * wr[i] * s_sh[i];
        // k-blocked layout: [k4][o][kin]
        outp[(i >> 2) * (OUT_C * 4) + t * 4 + (i & 3)] = v * demod;
    }
}

// ---------------------------------------------------------------------------
// Packed f32x2 FMA (PTX-only; ptxas never auto-fuses)
// ---------------------------------------------------------------------------
__device__ __forceinline__ void fma2(unsigned long long& d,
                                     unsigned long long a,
                                     unsigned long long b) {
    asm volatile("fma.rn.f32x2 %0, %1, %2, %0;" : "+l"(d) : "l"(a), "l"(b));
}
__device__ __forceinline__ float f2lo(unsigned long long v) {
    return __uint_as_float((unsigned)(v & 0xffffffffull));
}
__device__ __forceinline__ float f2hi(unsigned long long v) {
    return __uint_as_float((unsigned)(v >> 32));
}

// ---------------------------------------------------------------------------
// Kernel B: per-batch GEMM, CTA tile = 128 points x 64 outs, 256 threads.
// Thread tile = 8 points x 4 outputs; f32x2 vectorized over k (even/odd
// partial sums), so X stays in NATURAL [p][k] layout (no transpose, fully
// coalesced staging) and W needs NO duplication.
// ---------------------------------------------------------------------------
#define XPAD 68   // Xs row stride in floats (128+... keeps 16B alignment)

__global__ __launch_bounds__(256, 2)
void modconv_kernel(const float* __restrict__ x,
                    const float* __restrict__ bias,
                    float* __restrict__ out) {
    __shared__ __align__(16) float Xs[128][XPAD];      // ~34 KB, [p][k]
    __shared__ __align__(16) float Wt[16][OUT_C][4];   // 16 KB,  [k4][o][kin]

    const int b   = blockIdx.y;
    const int tid = threadIdx.x;
    const long base = ((long)b * N_PTS + (long)blockIdx.x * 128) * IN_C;

    // ---- stage X (fully coalesced: consecutive lanes read consecutive
    //      float4; STS lanes of one point write 256 contiguous bytes) ----
    {
        const float4* xin4 = (const float4*)(x + base);
        #pragma unroll
        for (int it = 0; it < 8; it++) {
            int idx = tid + it * 256;          // float4 id 0..2047
            int p   = idx >> 4;                // point 0..127
            int c4  = idx & 15;                // k-chunk 0..15
            float4 v = xin4[idx];
            *(float4*)&Xs[p][c4 * 4] = v;
        }
    }
    // ---- stage W tile (already k-blocked in g_W; straight copy) ----
    {
        const float4* Wb = (const float4*)(g_W + b * IN_C * OUT_C);
        float4* Wts = (float4*)Wt;
        #pragma unroll
        for (int it = 0; it < 4; it++) {
            int idx = tid + it * 256;          // 0..1023
            Wts[idx] = Wb[idx];
        }
    }
    __syncthreads();

    const int og = tid & 15;   const int o0 = og * 4;   // 16 out-groups of 4
    const int pg = tid >> 4;   const int p0 = pg * 8;   // 16 pt-groups of 8

    unsigned long long acc[8][4];              // [point][out], k-pair partials
    #pragma unroll
    for (int i = 0; i < 8; i++)
        #pragma unroll
        for (int j = 0; j < 4; j++) acc[i][j] = 0ull;

    #pragma unroll 2
    for (int k4 = 0; k4 < 16; k4++) {
        // W: 4 outputs x 4 k's = 4 x LDS.128, conflict-free (64 consecutive
        // 16B chunks across the warp's 16 og lanes)
        const ulonglong2* wp = (const ulonglong2*)&Wt[k4][o0][0];
        ulonglong2 w0 = wp[0];
        ulonglong2 w1 = wp[1];
        ulonglong2 w2 = wp[2];
        ulonglong2 w3 = wp[3];

        // X: 8 points x 4 k's = 8 x LDS.128 (16-lane broadcast each)
        #pragma unroll
        for (int i = 0; i < 8; i++) {
            ulonglong2 xa = *(const ulonglong2*)&Xs[p0 + i][k4 * 4];
            fma2(acc[i][0], xa.x, w0.x);
            fma2(acc[i][1], xa.x, w1.x);
            fma2(acc[i][2], xa.x, w2.x);
            fma2(acc[i][3], xa.x, w3.x);
            fma2(acc[i][0], xa.y, w0.y);
            fma2(acc[i][1], xa.y, w1.y);
            fma2(acc[i][2], xa.y, w2.y);
            fma2(acc[i][3], xa.y, w3.y);
        }
    }

    // ---- epilogue: fold k-pair partials, add bias, coalesced STG.128 ----
    float4 bv = *(const float4*)(bias + o0);
    float* op = out + base;
    #pragma unroll
    for (int i = 0; i < 8; i++) {
        float4 r;
        r.x = f2lo(acc[i][0]) + f2hi(acc[i][0]) + bv.x;
        r.y = f2lo(acc[i][1]) + f2hi(acc[i][1]) + bv.y;
        r.z = f2lo(acc[i][2]) + f2hi(acc[i][2]) + bv.z;
        r.w = f2lo(acc[i][3]) + f2hi(acc[i][3]) + bv.w;
        *(float4*)(op + (long)(p0 + i) * OUT_C + o0) = r;
    }
}

// ---------------------------------------------------------------------------
// Launch
// inputs: 0=x, 1=style, 2=weight, 3=bias, 4=mod_weight, 5=mod_bias
// ---------------------------------------------------------------------------
extern "C" void kernel_launch(void* const* d_in, const int* in_sizes, int n_in,
                              void* d_out, int out_size) {
    const float* x          = (const float*)d_in[0];
    const float* style      = (const float*)d_in[1];
    const float* weight     = (const float*)d_in[2];
    const float* bias       = (const float*)d_in[3];
    const float* mod_weight = (const float*)d_in[4];
    const float* mod_bias   = (const float*)d_in[5];
    float* out = (float*)d_out;

    modw_kernel<<<B_SZ, 64>>>(style, weight, mod_weight, mod_bias);

    dim3 grid(N_PTS / 128, B_SZ);
    modconv_kernel<<<grid, 256>>>(x, bias, out);
}

// round 12
// speedup vs baseline: 2.6373x; 2.4091x over previous
#include <cuda_runtime.h>
#include <cuda_bf16.h>
#include <cstdint>

// ---------------------------------------------------------------------------
// Problem constants
// ---------------------------------------------------------------------------
#define B_SZ     8
#define N_PTS    131072
#define IN_C     64
#define OUT_C    64
#define STYLE_D  256
#define EPS_V    1e-8f

#define TILE_M   128          // points per CTA
#define THREADS  256          // 8 warps: 4 m-groups x 2 n-groups

// Per-batch modulated weights, bf16-split, linear [o][k] (64x64 each)
__device__ __align__(16) __nv_bfloat16 g_Whi[B_SZ][OUT_C * IN_C];
__device__ __align__(16) __nv_bfloat16 g_Wlo[B_SZ][OUT_C * IN_C];

// ---------------------------------------------------------------------------
// Kernel A: build weights, split to bf16 hi/lo. Negligible cost.
// ---------------------------------------------------------------------------
__global__ void modw_kernel(const float* __restrict__ style,
                            const float* __restrict__ weight,
                            const float* __restrict__ mod_weight,
                            const float* __restrict__ mod_bias) {
    const int b = blockIdx.x;
    const int t = threadIdx.x;             // 0..63 = output channel o
    __shared__ float s_sh[IN_C];

    const float mod_scale = 0.0625f;       // 1/sqrt(256)
    const float* st = style + b * STYLE_D;
    const float* mw = mod_weight + t * STYLE_D;
    float acc = 0.f;
    #pragma unroll 8
    for (int d = 0; d < STYLE_D; d += 4) {
        float4 a = *(const float4*)(st + d);
        float4 m = *(const float4*)(mw + d);
        acc += a.x * m.x + a.y * m.y + a.z * m.z + a.w * m.w;
    }
    s_sh[t] = acc * mod_scale + mod_bias[t] + 1.0f;
    __syncthreads();

    const float scale = 0.125f;            // 1/sqrt(64)
    const float* wr = weight + t * IN_C;
    float ss = 0.f;
    #pragma unroll 16
    for (int i = 0; i < IN_C; i++) {
        float v = scale * wr[i] * s_sh[i];
        ss += v * v;
    }
    float demod = rsqrtf(ss + EPS_V);
    #pragma unroll 16
    for (int i = 0; i < IN_C; i++) {
        float v = scale * wr[i] * s_sh[i] * demod;
        __nv_bfloat16 vh = __float2bfloat16(v);
        __nv_bfloat16 vl = __float2bfloat16(v - __bfloat162float(vh));
        g_Whi[b][t * IN_C + i] = vh;
        g_Wlo[b][t * IN_C + i] = vl;
    }
}

// ---------------------------------------------------------------------------
// MMA / ldmatrix primitives (plain sm_80+ features; NO tcgen05 — the harness
// compiles a compute_103 (non-'a') PTX stage where tcgen05 is rejected).
// ---------------------------------------------------------------------------
__device__ __forceinline__ uint32_t smem_u32(const void* p) {
    uint32_t a;
    asm("{ .reg .u64 t; cvta.to.shared.u64 t, %1; cvt.u32.u64 %0, t; }"
        : "=r"(a) : "l"(p));
    return a;
}

#define LDSM4(r, a) \
    asm volatile("ldmatrix.sync.aligned.m8n8.x4.shared.b16 {%0,%1,%2,%3}, [%4];" \
        : "=r"((r)[0]), "=r"((r)[1]), "=r"((r)[2]), "=r"((r)[3]) : "r"(a))

#define MMA16816(c, a, b0, b1) \
    asm volatile("mma.sync.aligned.m16n8k16.row.col.f32.bf16.bf16.f32 " \
        "{%0,%1,%2,%3}, {%4,%5,%6,%7}, {%8,%9}, {%0,%1,%2,%3};" \
        : "+f"((c)[0]), "+f"((c)[1]), "+f"((c)[2]), "+f"((c)[3]) \
        : "r"((a)[0]), "r"((a)[1]), "r"((a)[2]), "r"((a)[3]), \
          "r"(b0), "r"(b1))

// ---------------------------------------------------------------------------
// SMEM layout. Pitch 144B (= 128+16) makes every ldmatrix phase conflict-free
// (row stride mod 128 = 16 walks all eight 16B bank groups).
// ---------------------------------------------------------------------------
#define W_PITCH   144
#define A_PITCH   144
#define SM_W_HI   0
#define SM_W_LO   (OUT_C * W_PITCH)                 //  9216
#define SM_A_HI   (SM_W_LO + OUT_C * W_PITCH)      // 18432
#define SM_A_LO   (SM_A_HI + TILE_M * A_PITCH)     // 36864
#define SM_TOTAL  (SM_A_LO + TILE_M * A_PITCH)     // 55296
// Output overlay aliases the A region after compute (needs 128*272 = 34816B)
#define OUT_OVL   SM_A_HI
#define OUT_PITCH 68                                // floats per row (272B)

// ---------------------------------------------------------------------------
// Kernel B: bf16x3 GEMM via mma.sync. CTA = 128 pts x 64 outs, K=64.
// Warp tile = 32 pts x 32 outs; Whi fragments hoisted to registers.
// ---------------------------------------------------------------------------
__global__ __launch_bounds__(THREADS, 2)
void modconv_mma(const float* __restrict__ x,
                 const float* __restrict__ bias,
                 float* __restrict__ out) {
    extern __shared__ __align__(16) char smem[];
    const uint32_t sb = smem_u32(smem);
    const int tid = threadIdx.x;
    const int wid = tid >> 5;
    const int lid = tid & 31;
    const int b   = blockIdx.y;
    const long gbase = ((long)b * N_PTS + (long)blockIdx.x * TILE_M) * IN_C;

    // ---- stage W tiles (linear gmem -> pitched smem) ----
    {
        const uint2* whi = (const uint2*)g_Whi[b];   // 8B = 4 bf16
        const uint2* wlo = (const uint2*)g_Wlo[b];
        #pragma unroll
        for (int it = 0; it < 4; it++) {
            int idx = tid + it * THREADS;            // 0..1023
            int o = idx >> 4, c = idx & 15;
            *(uint2*)(smem + SM_W_HI + o * W_PITCH + c * 8) = whi[idx];
            *(uint2*)(smem + SM_W_LO + o * W_PITCH + c * 8) = wlo[idx];
        }
    }
    // ---- stage X: coalesced fp32 load, split hi/lo bf16 ----
    {
        const float4* xin4 = (const float4*)(x + gbase);
        #pragma unroll
        for (int it = 0; it < 8; it++) {
            int idx = tid + it * THREADS;            // 0..2047
            int p = idx >> 4, c = idx & 15;          // point, k-chunk of 4
            float4 v = xin4[idx];
            __nv_bfloat162 h0 = __floats2bfloat162_rn(v.x, v.y);
            __nv_bfloat162 h1 = __floats2bfloat162_rn(v.z, v.w);
            float lx = v.x - __bfloat162float(__low2bfloat16(h0));
            float ly = v.y - __bfloat162float(__high2bfloat16(h0));
            float lz = v.z - __bfloat162float(__low2bfloat16(h1));
            float lw = v.w - __bfloat162float(__high2bfloat16(h1));
            __nv_bfloat162 l0 = __floats2bfloat162_rn(lx, ly);
            __nv_bfloat162 l1 = __floats2bfloat162_rn(lz, lw);
            uint2 uh, ul;
            uh.x = *(uint32_t*)&h0;  uh.y = *(uint32_t*)&h1;
            ul.x = *(uint32_t*)&l0;  ul.y = *(uint32_t*)&l1;
            *(uint2*)(smem + SM_A_HI + p * A_PITCH + c * 8) = uh;
            *(uint2*)(smem + SM_A_LO + p * A_PITCH + c * 8) = ul;
        }
    }
    __syncthreads();

    // ---- warp tiling ----
    const int mBase = (wid & 3) * 32;                // point rows
    const int oBase = (wid >> 2) * 32;               // output cols
    // ldmatrix per-lane address components (lane feeds matrix mi = lid>>3)
    const int mi    = lid >> 3;
    const int l7    = lid & 7;
    const int a_row = (mi & 1) * 8 + l7;             // A: m0/m2 rows0-7, m1/m3 rows8-15
    const int a_kh  = mi >> 1;                       //    m0/m1 k-lo,   m2/m3 k-hi
    const int w_row = (mi >> 1) * 8 + l7;            // W: m0/m1 o0-7,   m2/m3 o8-15
    const int w_kh  = mi & 1;                        //    m0/m2 k-lo,   m1/m3 k-hi

    // ---- hoist Whi fragments for all 4 k-steps (32 regs) ----
    uint32_t WH[4][2][4];
    #pragma unroll
    for (int ks = 0; ks < 4; ks++)
        #pragma unroll
        for (int nb = 0; nb < 2; nb++) {
            uint32_t a = sb + SM_W_HI + (oBase + nb * 16 + w_row) * W_PITCH
                       + ks * 32 + w_kh * 16;
            LDSM4(WH[ks][nb], a);
        }

    float C[2][4][4];
    #pragma unroll
    for (int i = 0; i < 2; i++)
        #pragma unroll
        for (int j = 0; j < 4; j++)
            #pragma unroll
            for (int q = 0; q < 4; q++) C[i][j][q] = 0.f;

    // ---- main loop: 4 k-steps, 24 HMMA each ----
    #pragma unroll
    for (int ks = 0; ks < 4; ks++) {
        uint32_t AH[2][4], AL[2][4], WL[2][4];
        #pragma unroll
        for (int mf = 0; mf < 2; mf++) {
            uint32_t off = (mBase + mf * 16 + a_row) * A_PITCH + ks * 32 + a_kh * 16;
            LDSM4(AH[mf], sb + SM_A_HI + off);
            LDSM4(AL[mf], sb + SM_A_LO + off);
        }
        #pragma unroll
        for (int nb = 0; nb < 2; nb++) {
            uint32_t a = sb + SM_W_LO + (oBase + nb * 16 + w_row) * W_PITCH
                       + ks * 32 + w_kh * 16;
            LDSM4(WL[nb], a);
        }
        #pragma unroll
        for (int mf = 0; mf < 2; mf++)
            #pragma unroll
            for (int nf = 0; nf < 4; nf++) {
                const int nb = nf >> 1, sel = (nf & 1) * 2;
                float* c = C[mf][nf];
                MMA16816(c, AH[mf], WH[ks][nb][sel], WH[ks][nb][sel + 1]);
                MMA16816(c, AL[mf], WH[ks][nb][sel], WH[ks][nb][sel + 1]);
                MMA16816(c, AH[mf], WL[nb][sel],     WL[nb][sel + 1]);
            }
    }

    // ---- epilogue: bias add, padded-SMEM overlay (aliases A), coalesced STG
    __syncthreads();                       // all warps done reading A region
    {
        float* ovl = (float*)(smem + OUT_OVL);
        const int g = lid >> 2, t2 = (lid & 3) * 2;
        #pragma unroll
        for (int mf = 0; mf < 2; mf++)
            #pragma unroll
            for (int nf = 0; nf < 4; nf++) {
                const int col = oBase + nf * 8 + t2;
                const float b0 = __ldg(bias + col);
                const float b1 = __ldg(bias + col + 1);
                const int r0 = mBase + mf * 16 + g;
                float* c = C[mf][nf];
                *(float2*)(ovl + r0 * OUT_PITCH + col) =
                    make_float2(c[0] + b0, c[1] + b1);
                *(float2*)(ovl + (r0 + 8) * OUT_PITCH + col) =
                    make_float2(c[2] + b0, c[3] + b1);
            }
    }
    __syncthreads();
    {
        const float* ovl = (const float*)(smem + OUT_OVL);
        float4* out4 = (float4*)(out + gbase);
        #pragma unroll
        for (int it = 0; it < 8; it++) {
            int idx = tid + it * THREADS;            // 0..2047
            int p = idx >> 4, c = idx & 15;
            out4[idx] = *(const float4*)(ovl + p * OUT_PITCH + c * 4);
        }
    }
}

// ---------------------------------------------------------------------------
// Launch
// inputs: 0=x, 1=style, 2=weight, 3=bias, 4=mod_weight, 5=mod_bias
// ---------------------------------------------------------------------------
extern "C" void kernel_launch(void* const* d_in, const int* in_sizes, int n_in,
                              void* d_out, int out_size) {
    const float* x          = (const float*)d_in[0];
    const float* style      = (const float*)d_in[1];
    const float* weight     = (const float*)d_in[2];
    const float* bias       = (const float*)d_in[3];
    const float* mod_weight = (const float*)d_in[4];
    const float* mod_bias   = (const float*)d_in[5];
    float* out = (float*)d_out;

    cudaFuncSetAttribute(modconv_mma,
                         cudaFuncAttributeMaxDynamicSharedMemorySize, SM_TOTAL);

    modw_kernel<<<B_SZ, 64>>>(style, weight, mod_weight, mod_bias);

    dim3 grid(N_PTS / TILE_M, B_SZ);
    modconv_mma<<<grid, THREADS, SM_TOTAL>>>(x, bias, out);
}

// round 13
// speedup vs baseline: 2.9190x; 1.1068x over previous
#include <cuda_runtime.h>
#include <cuda_bf16.h>
#include <cstdint>

// ---------------------------------------------------------------------------
// Problem constants
// ---------------------------------------------------------------------------
#define B_SZ     8
#define N_PTS    131072
#define IN_C     64
#define OUT_C    64
#define STYLE_D  256
#define EPS_V    1e-8f

#define TILE_M   128          // points per CTA
#define THREADS  256          // 8 warps: 4 m-groups x 2 n-groups

// Per-batch modulated weights, bf16-split, linear [o][k] (64x64 each)
__device__ __align__(16) __nv_bfloat16 g_Whi[B_SZ][OUT_C * IN_C];
__device__ __align__(16) __nv_bfloat16 g_Wlo[B_SZ][OUT_C * IN_C];

// ---------------------------------------------------------------------------
// Kernel A: build weights, split to bf16 hi/lo. Negligible cost.
// ---------------------------------------------------------------------------
__global__ void modw_kernel(const float* __restrict__ style,
                            const float* __restrict__ weight,
                            const float* __restrict__ mod_weight,
                            const float* __restrict__ mod_bias) {
    const int b = blockIdx.x;
    const int t = threadIdx.x;             // 0..63 = output channel o
    __shared__ float s_sh[IN_C];

    const float mod_scale = 0.0625f;       // 1/sqrt(256)
    const float* st = style + b * STYLE_D;
    const float* mw = mod_weight + t * STYLE_D;
    float acc = 0.f;
    #pragma unroll 8
    for (int d = 0; d < STYLE_D; d += 4) {
        float4 a = *(const float4*)(st + d);
        float4 m = *(const float4*)(mw + d);
        acc += a.x * m.x + a.y * m.y + a.z * m.z + a.w * m.w;
    }
    s_sh[t] = acc * mod_scale + mod_bias[t] + 1.0f;
    __syncthreads();

    const float scale = 0.125f;            // 1/sqrt(64)
    const float* wr = weight + t * IN_C;
    float ss = 0.f;
    #pragma unroll 16
    for (int i = 0; i < IN_C; i++) {
        float v = scale * wr[i] * s_sh[i];
        ss += v * v;
    }
    float demod = rsqrtf(ss + EPS_V);
    #pragma unroll 16
    for (int i = 0; i < IN_C; i++) {
        float v = scale * wr[i] * s_sh[i] * demod;
        __nv_bfloat16 vh = __float2bfloat16(v);
        __nv_bfloat16 vl = __float2bfloat16(v - __bfloat162float(vh));
        g_Whi[b][t * IN_C + i] = vh;
        g_Wlo[b][t * IN_C + i] = vl;
    }
}

// ---------------------------------------------------------------------------
// MMA / ldmatrix / cp.async primitives (plain sm_80+ features; NO tcgen05 —
// the harness compiles a compute_103 (non-'a') PTX stage).
// ---------------------------------------------------------------------------
__device__ __forceinline__ uint32_t smem_u32(const void* p) {
    uint32_t a;
    asm("{ .reg .u64 t; cvta.to.shared.u64 t, %1; cvt.u32.u64 %0, t; }"
        : "=r"(a) : "l"(p));
    return a;
}

#define LDSM4(r, a) \
    asm volatile("ldmatrix.sync.aligned.m8n8.x4.shared.b16 {%0,%1,%2,%3}, [%4];" \
        : "=r"((r)[0]), "=r"((r)[1]), "=r"((r)[2]), "=r"((r)[3]) : "r"(a))

#define MMA16816(c, a, b0, b1) \
    asm volatile("mma.sync.aligned.m16n8k16.row.col.f32.bf16.bf16.f32 " \
        "{%0,%1,%2,%3}, {%4,%5,%6,%7}, {%8,%9}, {%0,%1,%2,%3};" \
        : "+f"((c)[0]), "+f"((c)[1]), "+f"((c)[2]), "+f"((c)[3]) \
        : "r"((a)[0]), "r"((a)[1]), "r"((a)[2]), "r"((a)[3]), \
          "r"(b0), "r"(b1))

#define CP_ASYNC16(sdst, gsrc) \
    asm volatile("cp.async.ca.shared.global [%0], [%1], 16;" \
        :: "r"(sdst), "l"(gsrc) : "memory")
#define CP_COMMIT()  asm volatile("cp.async.commit_group;" ::: "memory")
#define CP_WAIT0()   asm volatile("cp.async.wait_group 0;"  ::: "memory")

// ---------------------------------------------------------------------------
// SMEM layout. Pitch 144B (= 128+16) makes every ldmatrix phase conflict-free
// (row stride mod 128 = 16 walks all eight 16B bank groups).
// W staged via cp.async in 16B chunks: two 8-row groups per 16B (o, o+?) —
// we copy W linearly in 16B units; 144 pitch / 16B unit => stage by pairs.
// ---------------------------------------------------------------------------
#define W_PITCH   144
#define A_PITCH   144
#define SM_W_HI   0
#define SM_W_LO   (OUT_C * W_PITCH)                 //  9216
#define SM_A_HI   (SM_W_LO + OUT_C * W_PITCH)      // 18432
#define SM_A_LO   (SM_A_HI + TILE_M * A_PITCH)     // 36864
#define SM_TOTAL  (SM_A_LO + TILE_M * A_PITCH)     // 55296
// Output overlay aliases the A region after compute (needs 128*272 = 34816B)
#define OUT_OVL   SM_A_HI
#define OUT_PITCH 68                                // floats per row (272B)

// ---------------------------------------------------------------------------
// Kernel B: bf16x3 GEMM via mma.sync. CTA = 128 pts x 64 outs, K=64.
// Warp tile = 32 pts x 32 outs. WH loaded per k-step (not hoisted) to fit
// 3 CTAs/SM; W staged with cp.async.
// ---------------------------------------------------------------------------
__global__ __launch_bounds__(THREADS, 3)
void modconv_mma(const float* __restrict__ x,
                 const float* __restrict__ bias,
                 float* __restrict__ out) {
    extern __shared__ __align__(16) char smem[];
    const uint32_t sb = smem_u32(smem);
    const int tid = threadIdx.x;
    const int wid = tid >> 5;
    const int lid = tid & 31;
    const int b   = blockIdx.y;
    const long gbase = ((long)b * N_PTS + (long)blockIdx.x * TILE_M) * IN_C;

    // ---- stage W tiles via cp.async (no register round-trip) ----
    // 64 rows x 128B data per image; copy 16B chunks: 8 chunks/row, 512/image
    {
        const char* whi = (const char*)g_Whi[b];
        const char* wlo = (const char*)g_Wlo[b];
        #pragma unroll
        for (int it = 0; it < 2; it++) {
            int idx = tid + it * THREADS;            // 0..511
            int o = idx >> 3, c = idx & 7;           // row, 16B chunk
            CP_ASYNC16(sb + SM_W_HI + o * W_PITCH + c * 16, whi + idx * 16);
            CP_ASYNC16(sb + SM_W_LO + o * W_PITCH + c * 16, wlo + idx * 16);
        }
        CP_COMMIT();
    }
    // ---- stage X: coalesced fp32 load, split hi/lo bf16 ----
    {
        const float4* xin4 = (const float4*)(x + gbase);
        #pragma unroll
        for (int it = 0; it < 8; it++) {
            int idx = tid + it * THREADS;            // 0..2047
            int p = idx >> 4, c = idx & 15;          // point, k-chunk of 4
            float4 v = xin4[idx];
            __nv_bfloat162 h0 = __floats2bfloat162_rn(v.x, v.y);
            __nv_bfloat162 h1 = __floats2bfloat162_rn(v.z, v.w);
            float lx = v.x - __bfloat162float(__low2bfloat16(h0));
            float ly = v.y - __bfloat162float(__high2bfloat16(h0));
            float lz = v.z - __bfloat162float(__low2bfloat16(h1));
            float lw = v.w - __bfloat162float(__high2bfloat16(h1));
            __nv_bfloat162 l0 = __floats2bfloat162_rn(lx, ly);
            __nv_bfloat162 l1 = __floats2bfloat162_rn(lz, lw);
            uint2 uh, ul;
            uh.x = *(uint32_t*)&h0;  uh.y = *(uint32_t*)&h1;
            ul.x = *(uint32_t*)&l0;  ul.y = *(uint32_t*)&l1;
            *(uint2*)(smem + SM_A_HI + p * A_PITCH + c * 8) = uh;
            *(uint2*)(smem + SM_A_LO + p * A_PITCH + c * 8) = ul;
        }
    }
    CP_WAIT0();
    __syncthreads();

    // ---- warp tiling ----
    const int mBase = (wid & 3) * 32;                // point rows
    const int oBase = (wid >> 2) * 32;               // output cols
    // ldmatrix per-lane address components (lane feeds matrix mi = lid>>3)
    const int mi    = lid >> 3;
    const int l7    = lid & 7;
    const int a_row = (mi & 1) * 8 + l7;             // A: m0/m2 rows0-7, m1/m3 rows8-15
    const int a_kh  = mi >> 1;                       //    m0/m1 k-lo,   m2/m3 k-hi
    const int w_row = (mi >> 1) * 8 + l7;            // W: m0/m1 o0-7,   m2/m3 o8-15
    const int w_kh  = mi & 1;                        //    m0/m2 k-lo,   m1/m3 k-hi

    float C[2][4][4];
    #pragma unroll
    for (int i = 0; i < 2; i++)
        #pragma unroll
        for (int j = 0; j < 4; j++)
            #pragma unroll
            for (int q = 0; q < 4; q++) C[i][j][q] = 0.f;

    // ---- main loop: 4 k-steps, 24 HMMA each; WH loaded per step ----
    #pragma unroll
    for (int ks = 0; ks < 4; ks++) {
        uint32_t AH[2][4], AL[2][4], WH[2][4], WL[2][4];
        #pragma unroll
        for (int mf = 0; mf < 2; mf++) {
            uint32_t off = (mBase + mf * 16 + a_row) * A_PITCH + ks * 32 + a_kh * 16;
            LDSM4(AH[mf], sb + SM_A_HI + off);
            LDSM4(AL[mf], sb + SM_A_LO + off);
        }
        #pragma unroll
        for (int nb = 0; nb < 2; nb++) {
            uint32_t woff = (oBase + nb * 16 + w_row) * W_PITCH + ks * 32 + w_kh * 16;
            LDSM4(WH[nb], sb + SM_W_HI + woff);
            LDSM4(WL[nb], sb + SM_W_LO + woff);
        }
        #pragma unroll
        for (int mf = 0; mf < 2; mf++)
            #pragma unroll
            for (int nf = 0; nf < 4; nf++) {
                const int nb = nf >> 1, sel = (nf & 1) * 2;
                float* c = C[mf][nf];
                MMA16816(c, AH[mf], WH[nb][sel], WH[nb][sel + 1]);
                MMA16816(c, AL[mf], WH[nb][sel], WH[nb][sel + 1]);
                MMA16816(c, AH[mf], WL[nb][sel], WL[nb][sel + 1]);
            }
    }

    // ---- epilogue: bias add, padded-SMEM overlay (aliases A), coalesced STG
    __syncthreads();                       // all warps done reading A region
    {
        float* ovl = (float*)(smem + OUT_OVL);
        const int g = lid >> 2, t2 = (lid & 3) * 2;
        #pragma unroll
        for (int mf = 0; mf < 2; mf++)
            #pragma unroll
            for (int nf = 0; nf < 4; nf++) {
                const int col = oBase + nf * 8 + t2;
                const float b0 = __ldg(bias + col);
                const float b1 = __ldg(bias + col + 1);
                const int r0 = mBase + mf * 16 + g;
                float* c = C[mf][nf];
                *(float2*)(ovl + r0 * OUT_PITCH + col) =
                    make_float2(c[0] + b0, c[1] + b1);
                *(float2*)(ovl + (r0 + 8) * OUT_PITCH + col) =
                    make_float2(c[2] + b0, c[3] + b1);
            }
    }
    __syncthreads();
    {
        const float* ovl = (const float*)(smem + OUT_OVL);
        float4* out4 = (float4*)(out + gbase);
        #pragma unroll
        for (int it = 0; it < 8; it++) {
            int idx = tid + it * THREADS;            // 0..2047
            int p = idx >> 4, c = idx & 15;
            out4[idx] = *(const float4*)(ovl + p * OUT_PITCH + c * 4);
        }
    }
}

// ---------------------------------------------------------------------------
// Launch
// inputs: 0=x, 1=style, 2=weight, 3=bias, 4=mod_weight, 5=mod_bias
// ---------------------------------------------------------------------------
extern "C" void kernel_launch(void* const* d_in, const int* in_sizes, int n_in,
                              void* d_out, int out_size) {
    const float* x          = (const float*)d_in[0];
    const float* style      = (const float*)d_in[1];
    const float* weight     = (const float*)d_in[2];
    const float* bias       = (const float*)d_in[3];
    const float* mod_weight = (const float*)d_in[4];
    const float* mod_bias   = (const float*)d_in[5];
    float* out = (float*)d_out;

    cudaFuncSetAttribute(modconv_mma,
                         cudaFuncAttributeMaxDynamicSharedMemorySize, SM_TOTAL);

    modw_kernel<<<B_SZ, 64>>>(style, weight, mod_weight, mod_bias);

    dim3 grid(N_PTS / TILE_M, B_SZ);
    modconv_mma<<<grid, THREADS, SM_TOTAL>>>(x, bias, out);
}